// round 2
// baseline (speedup 1.0000x reference)
#include <cuda_runtime.h>

// Diffusion_38929583571393: 10 iterations of x += 0.05 * (grad_x + grad_y + grad_z)
// on a (64, 1024, 1024) fp32 volume, torch.gradient semantics (central diff
// interior, one-sided at the two boundary slices of each axis).

#define NX 64
#define NY 1024
#define NZ 1024
#define SX (NY * NZ)   // x stride = 1048576
#define SY (NZ)        // y stride = 1024
#define COEFF 0.05f    // ALPHA * DT
#define NITER 10

// Ping-pong scratch (allocation-free per harness rules): 256 MB, zero-init bss.
__device__ float g_scratch[(size_t)NX * NY * NZ];

__device__ __forceinline__ float4 ld4(const float* __restrict__ p) {
    return *reinterpret_cast<const float4*>(p);
}
__device__ __forceinline__ void st4(float* __restrict__ p, float4 v) {
    *reinterpret_cast<float4*>(p) = v;
}

// Block tile: y = 8 rows, z = 128 floats (32 lanes * float4). Block marches
// the full x range keeping x-1/x/x+1 planes in registers, so each element is
// read cold from DRAM exactly once per iteration (y/z neighbor loads hit
// L1/L2 — the streamed plane is only 4 MB, far below the 126 MB L2).
__global__ __launch_bounds__(256, 4) void diff_step(const float* __restrict__ in,
                                                    float* __restrict__ out) {
    const int z = (blockIdx.x * 32 + threadIdx.x) << 2;       // 0..1020, step 4
    const int y = blockIdx.y * 8 + threadIdx.y;               // 0..1023
    const unsigned base = (unsigned)y * SY + (unsigned)z;

    const bool y_lo = (y == 0);
    const bool y_hi = (y == NY - 1);
    const bool z_lo = (z == 0);
    const bool z_hi = (z + 4 == NZ);

    // y-neighbor offsets relative to idx (clamped variants are never used
    // at the boundary because y_lo/y_hi select the one-sided branch).
    const float* __restrict__ pin = in + base;
    float* __restrict__ pout = out + base;

    float4 cc = ld4(pin);             // plane x = 0
    float4 cp = ld4(pin + SX);        // plane x = 1
    float4 cm = cc;                   // dummy until x >= 1

    #pragma unroll 1
    for (int x = 0; x < NX; ++x) {
        // ---- grad_x (axis 0, size 64) ----
        float4 gx;
        if (x == 0) {
            gx.x = cp.x - cc.x; gx.y = cp.y - cc.y;
            gx.z = cp.z - cc.z; gx.w = cp.w - cc.w;
        } else if (x == NX - 1) {
            gx.x = cc.x - cm.x; gx.y = cc.y - cm.y;
            gx.z = cc.z - cm.z; gx.w = cc.w - cm.w;
        } else {
            gx.x = 0.5f * (cp.x - cm.x); gx.y = 0.5f * (cp.y - cm.y);
            gx.z = 0.5f * (cp.z - cm.z); gx.w = 0.5f * (cp.w - cm.w);
        }

        // ---- grad_y (axis 1, size 1024) ----
        float4 gy;
        if (y_lo) {
            float4 yp = ld4(pin + SY);
            gy.x = yp.x - cc.x; gy.y = yp.y - cc.y;
            gy.z = yp.z - cc.z; gy.w = yp.w - cc.w;
        } else if (y_hi) {
            float4 ym = ld4(pin - SY);
            gy.x = cc.x - ym.x; gy.y = cc.y - ym.y;
            gy.z = cc.z - ym.z; gy.w = cc.w - ym.w;
        } else {
            float4 ym = ld4(pin - SY);
            float4 yp = ld4(pin + SY);
            gy.x = 0.5f * (yp.x - ym.x); gy.y = 0.5f * (yp.y - ym.y);
            gy.z = 0.5f * (yp.z - ym.z); gy.w = 0.5f * (yp.w - ym.w);
        }

        // ---- grad_z (axis 2, size 1024, contiguous) ----
        float zl = z_lo ? 0.0f : pin[-1];
        float zr = z_hi ? 0.0f : pin[4];
        float4 gz;
        gz.x = z_lo ? (cc.y - cc.x) : 0.5f * (cc.y - zl);
        gz.y = 0.5f * (cc.z - cc.x);
        gz.z = 0.5f * (cc.w - cc.y);
        gz.w = z_hi ? (cc.w - cc.z) : 0.5f * (zr - cc.z);

        float4 o;
        o.x = fmaf(COEFF, gx.x + gy.x + gz.x, cc.x);
        o.y = fmaf(COEFF, gx.y + gy.y + gz.y, cc.y);
        o.z = fmaf(COEFF, gx.z + gy.z + gz.z, cc.z);
        o.w = fmaf(COEFF, gx.w + gy.w + gz.w, cc.w);
        st4(pout, o);

        // rotate planes, stream the next one
        cm = cc;
        cc = cp;
        if (x + 2 < NX) cp = ld4(pin + 2 * SX);

        pin += SX;
        pout += SX;
    }
}

extern "C" void kernel_launch(void* const* d_in, const int* in_sizes, int n_in,
                              void* d_out, int out_size) {
    const float* x = (const float*)d_in[0];
    float* out = (float*)d_out;
    float* scratch = nullptr;
    cudaGetSymbolAddress((void**)&scratch, g_scratch);

    dim3 block(32, 8);
    dim3 grid(NZ / 128, NY / 8);   // 8 x 128 = 1024 blocks

    const float* src = x;
    for (int it = 0; it < NITER; ++it) {
        // even iters write scratch, odd write out -> iter 9 lands in d_out
        float* dst = (it & 1) ? out : scratch;
        diff_step<<<grid, block>>>(src, dst);
        src = dst;
    }
}